// round 1
// baseline (speedup 1.0000x reference)
#include <cuda_runtime.h>

// Quanvolution via closed-form expectation values (Heisenberg picture):
//   a0 = x0 + w0, a1 = x1 + w1
//   <Z0> = cos(w2) * cos(a0)
//   <Z1> = cos(a1)
//   <Z2> = cos(a0) * cos(x2)
//   <Z3> = cos(w3) * cos(a0) * cos(x2) * cos(x3)
//
// Input  x: [32, 1, 512, 512] fp32 ; patch(b,j,k) = {x[2j,2k], x[2j,2k+1], x[2j+1,2k], x[2j+1,2k+1]}
// Output  : [32, 4, 256, 256] fp32
//
// Each thread: one float4 from row 2j and one from row 2j+1 -> 2 adjacent
// patches -> one float2 store into each of the 4 output planes.

#define B_DIM   32
#define HP      256
#define WP      256
#define PLANE   (HP * WP)          // 65536
#define NTHREADS_TOTAL (B_DIM * HP * (WP / 2))  // 1,048,576

__global__ __launch_bounds__(256)
void quanv_kernel(const float* __restrict__ x,
                  const float* __restrict__ w,
                  float* __restrict__ out) {
    int idx = blockIdx.x * blockDim.x + threadIdx.x;   // [0, 1048576)
    int kk = idx & 127;            // which float4 within the row (2 patches)
    int j  = (idx >> 7) & 255;     // patch row
    int b  = idx >> 15;            // batch

    const float w0  = __ldg(w + 0);
    const float w1  = __ldg(w + 1);
    const float cw2 = __cosf(__ldg(w + 2));
    const float cw3 = __cosf(__ldg(w + 3));

    // input: rows 2j and 2j+1, columns [4*kk, 4*kk+4)
    const float4* row0 = reinterpret_cast<const float4*>(
        x + ((size_t)b * 512 + 2 * (size_t)j) * 512) + kk;
    const float4* row1 = row0 + 128;   // +512 floats = next row

    float4 r0 = __ldg(row0);
    float4 r1 = __ldg(row1);

    // patch A: (r0.x, r0.y, r1.x, r1.y); patch B: (r0.z, r0.w, r1.z, r1.w)
    float c0a = __cosf(r0.x + w0);
    float c1a = __cosf(r0.y + w1);
    float c2a = __cosf(r1.x);
    float c3a = __cosf(r1.y);

    float c0b = __cosf(r0.z + w0);
    float c1b = __cosf(r0.w + w1);
    float c2b = __cosf(r1.z);
    float c3b = __cosf(r1.w);

    float e2a = c0a * c2a;
    float e2b = c0b * c2b;

    size_t obase = (((size_t)b * 4) * HP + j) * WP + 2 * (size_t)kk;

    *reinterpret_cast<float2*>(out + obase)             = make_float2(cw2 * c0a, cw2 * c0b);
    *reinterpret_cast<float2*>(out + obase + PLANE)     = make_float2(c1a,        c1b);
    *reinterpret_cast<float2*>(out + obase + 2 * PLANE) = make_float2(e2a,        e2b);
    *reinterpret_cast<float2*>(out + obase + 3 * PLANE) = make_float2(cw3 * e2a * c3a,
                                                                      cw3 * e2b * c3b);
}

extern "C" void kernel_launch(void* const* d_in, const int* in_sizes, int n_in,
                              void* d_out, int out_size) {
    const float* x = (const float*)d_in[0];
    const float* w = (const float*)d_in[1];
    float* out = (float*)d_out;

    dim3 block(256);
    dim3 grid(NTHREADS_TOTAL / 256);   // 4096 blocks
    quanv_kernel<<<grid, block>>>(x, w, out);
}